// round 6
// baseline (speedup 1.0000x reference)
#include <cuda_runtime.h>
#include <cuda_bf16.h>
#include <cstdint>

// Inputs (metadata order):
//  0: bond_type   int32 [N_BONDS]
//  1: atom_i      int32 [N_BONDS]
//  2: bo_sigma    f32   [N_BONDS]
//  3: bo_pi       f32   [N_BONDS]
//  4: bo_pipi     f32   [N_BONDS]
//  5: bond_params f32   [16, 5]   (de_s, de_p, de_pp, p_be1, p_be2)
//  6: n_atoms     (scalar)
// Output: e_atom f32 [n_atoms]
//
// R6: move streaming reads off the L1tex wavefront path via cp.async.bulk
// (TMA) into SMEM; REDs keep the wavefront queue to themselves.

#define N_TYPES 16
#define LOG2E 1.4426950408889634f

#define TILE 2048          // bonds per CTA
#define TPB  256           // threads per block
#define ARR_BYTES (TILE * 4)   // 8192 B per stream per tile

// smem layout (dynamic):
//   [0:8)        mbarrier
//   [128 + k*8192)  stream k tile (k = 0..4: bt, ai, s, pi, pp)
//   [41088)      param LUT (128 floats)
#define SM_MBAR 0
#define SM_DATA 128
#define SM_LUT  (SM_DATA + 5 * ARR_BYTES)
#define SM_TOTAL (SM_LUT + 128 * 4)

__device__ __forceinline__ float ex2f(float x) {
    float y; asm("ex2.approx.ftz.f32 %0, %1;" : "=f"(y) : "f"(x)); return y;
}
__device__ __forceinline__ float lg2f(float x) {
    float y; asm("lg2.approx.ftz.f32 %0, %1;" : "=f"(y) : "f"(x)); return y;
}

__device__ __forceinline__ uint32_t smem_u32(const void* p) {
    uint32_t a;
    asm("{ .reg .u64 t; cvta.to.shared.u64 t, %1; cvt.u32.u64 %0, t; }"
        : "=r"(a) : "l"(p));
    return a;
}

__device__ __forceinline__ void mbar_init(uint32_t mbar, uint32_t count) {
    asm volatile("mbarrier.init.shared.b64 [%0], %1;" :: "r"(mbar), "r"(count) : "memory");
}
__device__ __forceinline__ void mbar_expect_tx(uint32_t mbar, uint32_t bytes) {
    asm volatile("mbarrier.arrive.expect_tx.shared.b64 _, [%0], %1;"
                 :: "r"(mbar), "r"(bytes) : "memory");
}
__device__ __forceinline__ void bulk_ld(uint32_t dst, const void* src, uint32_t bytes, uint32_t mbar) {
    asm volatile(
        "cp.async.bulk.shared::cluster.global.mbarrier::complete_tx::bytes [%0], [%1], %2, [%3];"
        :: "r"(dst), "l"(src), "r"(bytes), "r"(mbar) : "memory");
}
__device__ __forceinline__ void mbar_wait(uint32_t mbar, uint32_t parity) {
    asm volatile(
        "{\n\t"
        ".reg .pred P1;\n\t"
        "WAIT_LOOP_%=:\n\t"
        "mbarrier.try_wait.parity.acquire.cta.shared::cta.b64 P1, [%0], %1, 0x989680;\n\t"
        "@P1 bra.uni WAIT_DONE_%=;\n\t"
        "bra.uni WAIT_LOOP_%=;\n\t"
        "WAIT_DONE_%=:\n\t"
        "}"
        :: "r"(mbar), "r"(parity) : "memory");
}

__global__ __launch_bounds__(TPB) void reaxff_bond_energy_tma_kernel(
    const int*   __restrict__ bond_type,
    const int*   __restrict__ atom_i,
    const float* __restrict__ bo_sigma,
    const float* __restrict__ bo_pi,
    const float* __restrict__ bo_pipi,
    const float* __restrict__ bond_params,  // [16,5]
    float*       __restrict__ e_atom)
{
    extern __shared__ __align__(128) unsigned char smem[];
    uint32_t base = smem_u32(smem);
    float* s_par = reinterpret_cast<float*>(smem + SM_LUT);
    int tid = threadIdx.x;

    // Param LUT, padded stride 8:
    //   [0]=de_s [1]=p_be1*log2e [2]=p_be2 [4]=de_p [5]=de_pp
    if (tid < N_TYPES) {
        s_par[tid * 8 + 0] = bond_params[tid * 5 + 0];
        s_par[tid * 8 + 1] = bond_params[tid * 5 + 3] * LOG2E;
        s_par[tid * 8 + 2] = bond_params[tid * 5 + 4];
        s_par[tid * 8 + 3] = 0.0f;
        s_par[tid * 8 + 4] = bond_params[tid * 5 + 1];
        s_par[tid * 8 + 5] = bond_params[tid * 5 + 2];
        s_par[tid * 8 + 6] = 0.0f;
        s_par[tid * 8 + 7] = 0.0f;
    }

    if (tid == 0) mbar_init(base + SM_MBAR, 1);
    __syncthreads();   // mbar init + LUT visible

    long long tile_base = (long long)blockIdx.x * TILE;
    if (tid == 0) {
        mbar_expect_tx(base + SM_MBAR, 5 * ARR_BYTES);
        bulk_ld(base + SM_DATA + 0 * ARR_BYTES, bond_type + tile_base, ARR_BYTES, base + SM_MBAR);
        bulk_ld(base + SM_DATA + 1 * ARR_BYTES, atom_i    + tile_base, ARR_BYTES, base + SM_MBAR);
        bulk_ld(base + SM_DATA + 2 * ARR_BYTES, bo_sigma  + tile_base, ARR_BYTES, base + SM_MBAR);
        bulk_ld(base + SM_DATA + 3 * ARR_BYTES, bo_pi     + tile_base, ARR_BYTES, base + SM_MBAR);
        bulk_ld(base + SM_DATA + 4 * ARR_BYTES, bo_pipi   + tile_base, ARR_BYTES, base + SM_MBAR);
    }
    mbar_wait(base + SM_MBAR, 0);

    const int4*   sbt = reinterpret_cast<const int4*>(smem + SM_DATA + 0 * ARR_BYTES);
    const int4*   sai = reinterpret_cast<const int4*>(smem + SM_DATA + 1 * ARR_BYTES);
    const float4* sbs = reinterpret_cast<const float4*>(smem + SM_DATA + 2 * ARR_BYTES);
    const float4* sbp = reinterpret_cast<const float4*>(smem + SM_DATA + 3 * ARR_BYTES);
    const float4* sbq = reinterpret_cast<const float4*>(smem + SM_DATA + 4 * ARR_BYTES);

    // 8 bonds per thread: two float4/int4 reads per stream.
#pragma unroll
    for (int half = 0; half < 2; half++) {
        int q = tid * 2 + half;       // quad index in tile
        int4   bt = sbt[q];
        int4   ai = sai[q];
        float4 bs = sbs[q];
        float4 bp = sbp[q];
        float4 bq = sbq[q];

        const int   t[4]  = {bt.x, bt.y, bt.z, bt.w};
        const int   a[4]  = {ai.x, ai.y, ai.z, ai.w};
        const float s[4]  = {bs.x, bs.y, bs.z, bs.w};
        const float pi[4] = {bp.x, bp.y, bp.z, bp.w};
        const float pp[4] = {bq.x, bq.y, bq.z, bq.w};

#pragma unroll
        for (int k = 0; k < 4; k++) {
            float de_s    = s_par[t[k] * 8 + 0];
            float p_be1l2 = s_par[t[k] * 8 + 1];
            float p_be2   = s_par[t[k] * 8 + 2];
            float de_p    = s_par[t[k] * 8 + 4];
            float de_pp   = s_par[t[k] * 8 + 5];

            float pow_s = ex2f(p_be2 * lg2f(s[k]));
            float lin   = fmaf(de_p, pi[k], de_pp * pp[k]);
            float e     = fmaf(-de_s * s[k], ex2f(p_be1l2 * (1.0f - pow_s)), -lin);

            atomicAdd(&e_atom[a[k]], e);  // return unused -> RED.E.ADD.F32
        }
    }
}

// Scalar tail for n_bonds % TILE (not expected for 2^24, kept for safety).
__global__ void reaxff_tail_kernel(
    const int* bond_type, const int* atom_i,
    const float* bo_sigma, const float* bo_pi, const float* bo_pipi,
    const float* bond_params, float* e_atom, int start, int n)
{
    int i = start + blockIdx.x * blockDim.x + threadIdx.x;
    if (i >= n) return;
    int t = bond_type[i];
    float de_s  = bond_params[t * 5 + 0];
    float de_p  = bond_params[t * 5 + 1];
    float de_pp = bond_params[t * 5 + 2];
    float p_be1 = bond_params[t * 5 + 3];
    float p_be2 = bond_params[t * 5 + 4];
    float s = bo_sigma[i];
    float pow_s = ex2f(p_be2 * lg2f(s));
    float e = -de_s * s * ex2f(p_be1 * LOG2E * (1.0f - pow_s))
              - de_p * bo_pi[i] - de_pp * bo_pipi[i];
    atomicAdd(&e_atom[atom_i[i]], e);
}

extern "C" void kernel_launch(void* const* d_in, const int* in_sizes, int n_in,
                              void* d_out, int out_size) {
    const int*   bond_type   = (const int*)  d_in[0];
    const int*   atom_i      = (const int*)  d_in[1];
    const float* bo_sigma    = (const float*)d_in[2];
    const float* bo_pi       = (const float*)d_in[3];
    const float* bo_pipi     = (const float*)d_in[4];
    const float* bond_params = (const float*)d_in[5];
    float* e_atom = (float*)d_out;

    int n_bonds = in_sizes[0];
    int n_atoms = out_size;

    // Zero the (poisoned) accumulator via a memset node (graph-capturable).
    cudaMemsetAsync(e_atom, 0, (size_t)n_atoms * sizeof(float));

    int n_tiles = n_bonds / TILE;          // 16777216 / 2048 = 8192
    if (n_tiles > 0) {
        reaxff_bond_energy_tma_kernel<<<n_tiles, TPB, SM_TOTAL>>>(
            bond_type, atom_i, bo_sigma, bo_pi, bo_pipi, bond_params, e_atom);
    }
    int done = n_tiles * TILE;
    if (done < n_bonds) {
        int rem = n_bonds - done;
        reaxff_tail_kernel<<<(rem + 255) / 256, 256>>>(
            bond_type, atom_i, bo_sigma, bo_pi, bo_pipi,
            bond_params, e_atom, done, n_bonds);
    }
}

// round 7
// speedup vs baseline: 1.0511x; 1.0511x over previous
#include <cuda_runtime.h>
#include <cuda_bf16.h>

// Inputs (metadata order):
//  0: bond_type   int32 [N_BONDS]
//  1: atom_i      int32 [N_BONDS]
//  2: bo_sigma    f32   [N_BONDS]
//  3: bo_pi       f32   [N_BONDS]
//  4: bo_pipi     f32   [N_BONDS]
//  5: bond_params f32   [16, 5]   (de_s, de_p, de_pp, p_be1, p_be2)
//  6: n_atoms     (scalar)
// Output: e_atom f32 [n_atoms]
//
// Established bottleneck (R1-R6): chip-wide LTS throughput cap consumed by
// 16.7M atomic RMWs (~1.07 GB internal L2 traffic) + 0.34 GB streaming
// reads. Six kernel shapes (wide, scalar, predicated-RED split, TMA+LDS)
// all land 107-113 us. This is the measured-best configuration (R1 shape).

#define N_TYPES 16
#define LOG2E 1.4426950408889634f

__device__ __forceinline__ float ex2f(float x) {
    float y; asm("ex2.approx.ftz.f32 %0, %1;" : "=f"(y) : "f"(x)); return y;
}
__device__ __forceinline__ float lg2f(float x) {
    float y; asm("lg2.approx.ftz.f32 %0, %1;" : "=f"(y) : "f"(x)); return y;
}

__global__ void zero_out_kernel(float4* __restrict__ out, int n4) {
    int i = blockIdx.x * blockDim.x + threadIdx.x;
    if (i < n4) out[i] = make_float4(0.f, 0.f, 0.f, 0.f);
}

__global__ __launch_bounds__(256) void reaxff_bond_energy_kernel(
    const int4*   __restrict__ bond_type4,
    const int4*   __restrict__ atom_i4,
    const float4* __restrict__ bo_s4,
    const float4* __restrict__ bo_p4,
    const float4* __restrict__ bo_pp4,
    const float*  __restrict__ bond_params,  // [16,5]
    float*        __restrict__ e_atom,
    int n_quads)
{
    // Padded LUT, stride 8 floats per type:
    //   [0]=de_s  [1]=p_be1*log2e  [2]=p_be2  [4]=de_p  [5]=de_pp
    __shared__ float s_par[N_TYPES * 8];
    if (threadIdx.x < N_TYPES) {
        int t = threadIdx.x;
        s_par[t * 8 + 0] = bond_params[t * 5 + 0];
        s_par[t * 8 + 1] = bond_params[t * 5 + 3] * LOG2E;
        s_par[t * 8 + 2] = bond_params[t * 5 + 4];
        s_par[t * 8 + 3] = 0.0f;
        s_par[t * 8 + 4] = bond_params[t * 5 + 1];
        s_par[t * 8 + 5] = bond_params[t * 5 + 2];
        s_par[t * 8 + 6] = 0.0f;
        s_par[t * 8 + 7] = 0.0f;
    }
    __syncthreads();

    int i = blockIdx.x * blockDim.x + threadIdx.x;
    if (i >= n_quads) return;

    // Front-batched independent wide loads (MLP=5).
    int4   bt = bond_type4[i];
    int4   ai = atom_i4[i];
    float4 bs = bo_s4[i];
    float4 bp = bo_p4[i];
    float4 bq = bo_pp4[i];

    const int   t[4]  = {bt.x, bt.y, bt.z, bt.w};
    const int   a[4]  = {ai.x, ai.y, ai.z, ai.w};
    const float s[4]  = {bs.x, bs.y, bs.z, bs.w};
    const float pi[4] = {bp.x, bp.y, bp.z, bp.w};
    const float pp[4] = {bq.x, bq.y, bq.z, bq.w};

#pragma unroll
    for (int k = 0; k < 4; k++) {
        float de_s    = s_par[t[k] * 8 + 0];
        float p_be1l2 = s_par[t[k] * 8 + 1];
        float p_be2   = s_par[t[k] * 8 + 2];
        float de_p    = s_par[t[k] * 8 + 4];
        float de_pp   = s_par[t[k] * 8 + 5];

        // s^p_be2 = 2^(p_be2*log2 s);  exp(p_be1*(1-x)) = 2^(p_be1l2*(1-x))
        float pow_s = ex2f(p_be2 * lg2f(s[k]));
        float lin   = fmaf(de_p, pi[k], de_pp * pp[k]);
        float e     = fmaf(-de_s * s[k], ex2f(p_be1l2 * (1.0f - pow_s)), -lin);

        atomicAdd(&e_atom[a[k]], e);  // return unused -> RED.E.ADD.F32
    }
}

extern "C" void kernel_launch(void* const* d_in, const int* in_sizes, int n_in,
                              void* d_out, int out_size) {
    const int*   bond_type   = (const int*)  d_in[0];
    const int*   atom_i      = (const int*)  d_in[1];
    const float* bo_sigma    = (const float*)d_in[2];
    const float* bo_pi       = (const float*)d_in[3];
    const float* bo_pipi     = (const float*)d_in[4];
    const float* bond_params = (const float*)d_in[5];
    float* e_atom = (float*)d_out;

    int n_bonds = in_sizes[0];
    int n_atoms = out_size;

    // Zero the (poisoned) accumulator (R1 envelope: zero kernel, not memset).
    int n4_out = n_atoms / 4;              // n_atoms = 2^20, divisible by 4
    zero_out_kernel<<<(n4_out + 255) / 256, 256>>>((float4*)e_atom, n4_out);

    int n_quads = n_bonds / 4;             // 16777216 / 4
    int threads = 256;
    int blocks  = (n_quads + threads - 1) / threads;
    reaxff_bond_energy_kernel<<<blocks, threads>>>(
        (const int4*)bond_type, (const int4*)atom_i,
        (const float4*)bo_sigma, (const float4*)bo_pi, (const float4*)bo_pipi,
        bond_params, e_atom, n_quads);
}